// round 7
// baseline (speedup 1.0000x reference)
#include <cuda_runtime.h>
#include <cuda_fp16.h>
#include <cuda_bf16.h>
#include <cstdint>

// ChannelSelfAttention: B=4,H=512,W=256. 2048 independent W x W attentions
// over a 2-channel feature. One CTA per (b,h), 128 threads; each thread owns
// TWO query positions (t, t+128).
//
// Full f16x2 inner loop: k/v stored packed __half2 in smem; scores (HFMA2),
// exp (ex2.approx.f16x2 via h2exp2), and AV accumulation (HADD2/HFMA2) all
// process 2 keys per instruction with ZERO converts in the hot loop (R5
// showed per-pair cvts land on the xu pipe and erase the MUFU win).
// f16 accumulators are spilled to f32 every 32 keys (chunked outer loop,
// no runtime branch in the hot body) to bound accumulation error.

#define W_DIM 256
#define BH_TOTAL 2048
#define PLANE (2048 * 256)

__global__ __launch_bounds__(128) void channel_attn_kernel(
    const float* __restrict__ x1, const float* __restrict__ x2,
    const float* __restrict__ wq, const float* __restrict__ bq,
    const float* __restrict__ wk, const float* __restrict__ bk,
    const float* __restrict__ wv, const float* __restrict__ bv,
    float* __restrict__ out)
{
    const int tid  = threadIdx.x;
    const int base = blockIdx.x * W_DIM;

    // Quad layout (quad = 4 keys): 16-bit index 8*quad + 2*pairIdx + half
    // for channel 0; +4 for channel 1. One uint4 (LDS.128) per quad/channel.
    __shared__ __align__(16) __half kArrH[2 * W_DIM];
    __shared__ __align__(16) __half vArrH[2 * W_DIM];
    __shared__ float red[8];

    const float aA = x1[base + tid];
    const float bA = x2[base + tid];
    const float aB = x1[base + tid + 128];
    const float bB = x2[base + tid + 128];

    const float w_q0 = wq[0], w_q1 = wq[1], w_q2 = wq[2], w_q3 = wq[3];
    const float w_k0 = wk[0], w_k1 = wk[1], w_k2 = wk[2], w_k3 = wk[3];
    const float w_v0 = wv[0], w_v1 = wv[1], w_v2 = wv[2], w_v3 = wv[3];
    const float b_q0 = bq[0], b_q1 = bq[1];
    const float b_k0 = bk[0], b_k1 = bk[1];
    const float b_v0 = bv[0], b_v1 = bv[1];

    const float qA0 = fmaf(w_q0, aA, fmaf(w_q1, bA, b_q0));
    const float qA1 = fmaf(w_q2, aA, fmaf(w_q3, bA, b_q1));
    const float kA0 = fmaf(w_k0, aA, fmaf(w_k1, bA, b_k0));
    const float kA1 = fmaf(w_k2, aA, fmaf(w_k3, bA, b_k1));
    const float vA0 = fmaf(w_v0, aA, fmaf(w_v1, bA, b_v0));
    const float vA1 = fmaf(w_v2, aA, fmaf(w_v3, bA, b_v1));

    const float qB0 = fmaf(w_q0, aB, fmaf(w_q1, bB, b_q0));
    const float qB1 = fmaf(w_q2, aB, fmaf(w_q3, bB, b_q1));
    const float kB0 = fmaf(w_k0, aB, fmaf(w_k1, bB, b_k0));
    const float kB1 = fmaf(w_k2, aB, fmaf(w_k3, bB, b_k1));
    const float vB0 = fmaf(w_v0, aB, fmaf(w_v1, bB, b_v0));
    const float vB1 = fmaf(w_v2, aB, fmaf(w_v3, bB, b_v1));

    {
        int w = tid;
        int i0 = 8 * (w >> 2) + 2 * ((w >> 1) & 1) + (w & 1);
        kArrH[i0]     = __float2half(kA0);
        kArrH[i0 + 4] = __float2half(kA1);
        vArrH[i0]     = __float2half(vA0);
        vArrH[i0 + 4] = __float2half(vA1);
        w = tid + 128;
        i0 = 8 * (w >> 2) + 2 * ((w >> 1) & 1) + (w & 1);
        kArrH[i0]     = __float2half(kB0);
        kArrH[i0 + 4] = __float2half(kB1);
        vArrH[i0]     = __float2half(vB0);
        vArrH[i0 + 4] = __float2half(vB1);
    }

    // per-CTA max|k0|, max|k1| for the overflow-safe softmax bound
    float ak0 = fmaxf(fabsf(kA0), fabsf(kB0));
    float ak1 = fmaxf(fabsf(kA1), fabsf(kB1));
#pragma unroll
    for (int o = 16; o; o >>= 1) {
        ak0 = fmaxf(ak0, __shfl_xor_sync(0xffffffffu, ak0, o));
        ak1 = fmaxf(ak1, __shfl_xor_sync(0xffffffffu, ak1, o));
    }
    const int wid = tid >> 5;
    if ((tid & 31) == 0) { red[wid] = ak0; red[4 + wid] = ak1; }
    __syncthreads();

    float mk0 = fmaxf(fmaxf(red[0], red[1]), fmaxf(red[2], red[3]));
    float mk1 = fmaxf(fmaxf(red[4], red[5]), fmaxf(red[6], red[7]));

    const float L2E = 1.4426950408889634f;
    const float qA0e = qA0 * L2E, qA1e = qA1 * L2E;
    const float qB0e = qB0 * L2E, qB1e = qB1 * L2E;
    const float mhatA = fmaf(fabsf(qA0e), mk0, fabsf(qA1e) * mk1);
    const float mhatB = fmaf(fabsf(qB0e), mk0, fabsf(qB1e) * mk1);

    const __half2 qA0h = __float2half2_rn(qA0e);
    const __half2 qA1h = __float2half2_rn(qA1e);
    const __half2 qB0h = __float2half2_rn(qB0e);
    const __half2 qB1h = __float2half2_rn(qB1e);
    const __half2 mnAh = __float2half2_rn(-mhatA);
    const __half2 mnBh = __float2half2_rn(-mhatB);

    const uint4* kq4 = reinterpret_cast<const uint4*>(kArrH);
    const uint4* vq4 = reinterpret_cast<const uint4*>(vArrH);

    float fsA = 0.f, fA0 = 0.f, fA1 = 0.f;
    float fsB = 0.f, fB0 = 0.f, fB1 = 0.f;
    const __half2 hz = __float2half2_rn(0.f);

#pragma unroll 1
    for (int ch = 0; ch < 8; ++ch) {   // 8 chunks x 32 keys
        __half2 hsA = hz, hA0 = hz, hA1 = hz;
        __half2 hsB = hz, hB0 = hz, hB1 = hz;
#pragma unroll
        for (int j = 0; j < 8; ++j) {  // 8 quads of 4 keys (2 half2 pairs)
            const int qd = ch * 8 + j;
            const uint4 kk = kq4[qd];
            const uint4 vv = vq4[qd];
            const __half2 k0a = *reinterpret_cast<const __half2*>(&kk.x);
            const __half2 k0b = *reinterpret_cast<const __half2*>(&kk.y);
            const __half2 k1a = *reinterpret_cast<const __half2*>(&kk.z);
            const __half2 k1b = *reinterpret_cast<const __half2*>(&kk.w);
            const __half2 v0a = *reinterpret_cast<const __half2*>(&vv.x);
            const __half2 v0b = *reinterpret_cast<const __half2*>(&vv.y);
            const __half2 v1a = *reinterpret_cast<const __half2*>(&vv.z);
            const __half2 v1b = *reinterpret_cast<const __half2*>(&vv.w);

            const __half2 eAa = h2exp2(__hfma2(qA0h, k0a, __hfma2(qA1h, k1a, mnAh)));
            const __half2 eAb = h2exp2(__hfma2(qA0h, k0b, __hfma2(qA1h, k1b, mnAh)));
            const __half2 eBa = h2exp2(__hfma2(qB0h, k0a, __hfma2(qB1h, k1a, mnBh)));
            const __half2 eBb = h2exp2(__hfma2(qB0h, k0b, __hfma2(qB1h, k1b, mnBh)));

            hsA = __hadd2(hsA, eAa);  hsA = __hadd2(hsA, eAb);
            hsB = __hadd2(hsB, eBa);  hsB = __hadd2(hsB, eBb);
            hA0 = __hfma2(eAa, v0a, hA0);  hA0 = __hfma2(eAb, v0b, hA0);
            hA1 = __hfma2(eAa, v1a, hA1);  hA1 = __hfma2(eAb, v1b, hA1);
            hB0 = __hfma2(eBa, v0a, hB0);  hB0 = __hfma2(eBb, v0b, hB0);
            hB1 = __hfma2(eBa, v1a, hB1);  hB1 = __hfma2(eBb, v1b, hB1);
        }
        // spill chunk partials to f32
        float2 t;
        t = __half22float2(hsA); fsA += t.x + t.y;
        t = __half22float2(hA0); fA0 += t.x + t.y;
        t = __half22float2(hA1); fA1 += t.x + t.y;
        t = __half22float2(hsB); fsB += t.x + t.y;
        t = __half22float2(hB0); fB0 += t.x + t.y;
        t = __half22float2(hB1); fB1 += t.x + t.y;
    }

    float invA, invB;
    asm("rcp.approx.ftz.f32 %0, %1;" : "=f"(invA) : "f"(fsA));
    asm("rcp.approx.ftz.f32 %0, %1;" : "=f"(invB) : "f"(fsB));

    out[base + tid]               = fmaf(fA0, invA, aA);
    out[PLANE + base + tid]       = fmaf(fA1, invA, bA);
    out[base + tid + 128]         = fmaf(fB0, invB, aB);
    out[PLANE + base + tid + 128] = fmaf(fB1, invB, bB);
}

extern "C" void kernel_launch(void* const* d_in, const int* in_sizes, int n_in,
                              void* d_out, int out_size)
{
    (void)in_sizes; (void)n_in; (void)out_size;
    channel_attn_kernel<<<BH_TOTAL, 128>>>(
        (const float*)d_in[0], (const float*)d_in[1],
        (const float*)d_in[2], (const float*)d_in[3],
        (const float*)d_in[4], (const float*)d_in[5],
        (const float*)d_in[6], (const float*)d_in[7],
        (float*)d_out);
}

// round 8
// speedup vs baseline: 1.0069x; 1.0069x over previous
#include <cuda_runtime.h>
#include <cuda_fp16.h>
#include <cuda_bf16.h>
#include <cstdint>

// ChannelSelfAttention: B=4,H=512,W=256. 2048 independent W x W attentions
// over a 2-channel feature. One CTA per (b,h), 128 threads; each thread owns
// TWO query positions (t, t+128).
//
// f16x2 inner loop v2: scores (HFMA2), exp (ex2.approx.f16x2), accumulation
// (HADD2/HFMA2) all handle 2 keys/instr, zero converts in the hot loop.
// v2 stall fixes vs R6: dual accumulator banks (halved dep chains), 64-key
// chunks (4 spill fences instead of 8), direct half2 smem loads (no uint4
// reinterpret moves), wide unrolled window for LDS/EX2 overlap.

#define W_DIM 256
#define BH_TOTAL 2048
#define PLANE (2048 * 256)

__global__ __launch_bounds__(128) void channel_attn_kernel(
    const float* __restrict__ x1, const float* __restrict__ x2,
    const float* __restrict__ wq, const float* __restrict__ bq,
    const float* __restrict__ wk, const float* __restrict__ bk,
    const float* __restrict__ wv, const float* __restrict__ bv,
    float* __restrict__ out)
{
    const int tid  = threadIdx.x;
    const int base = blockIdx.x * W_DIM;

    // Pair-major half2 arrays: index j holds keys (2j, 2j+1).
    __shared__ __align__(16) __half2 k0s[W_DIM / 2];
    __shared__ __align__(16) __half2 k1s[W_DIM / 2];
    __shared__ __align__(16) __half2 v0s[W_DIM / 2];
    __shared__ __align__(16) __half2 v1s[W_DIM / 2];
    __shared__ float red[8];

    const float aA = x1[base + tid];
    const float bA = x2[base + tid];
    const float aB = x1[base + tid + 128];
    const float bB = x2[base + tid + 128];

    const float w_q0 = wq[0], w_q1 = wq[1], w_q2 = wq[2], w_q3 = wq[3];
    const float w_k0 = wk[0], w_k1 = wk[1], w_k2 = wk[2], w_k3 = wk[3];
    const float w_v0 = wv[0], w_v1 = wv[1], w_v2 = wv[2], w_v3 = wv[3];
    const float b_q0 = bq[0], b_q1 = bq[1];
    const float b_k0 = bk[0], b_k1 = bk[1];
    const float b_v0 = bv[0], b_v1 = bv[1];

    const float qA0 = fmaf(w_q0, aA, fmaf(w_q1, bA, b_q0));
    const float qA1 = fmaf(w_q2, aA, fmaf(w_q3, bA, b_q1));
    const float kA0 = fmaf(w_k0, aA, fmaf(w_k1, bA, b_k0));
    const float kA1 = fmaf(w_k2, aA, fmaf(w_k3, bA, b_k1));
    const float vA0 = fmaf(w_v0, aA, fmaf(w_v1, bA, b_v0));
    const float vA1 = fmaf(w_v2, aA, fmaf(w_v3, bA, b_v1));

    const float qB0 = fmaf(w_q0, aB, fmaf(w_q1, bB, b_q0));
    const float qB1 = fmaf(w_q2, aB, fmaf(w_q3, bB, b_q1));
    const float kB0 = fmaf(w_k0, aB, fmaf(w_k1, bB, b_k0));
    const float kB1 = fmaf(w_k2, aB, fmaf(w_k3, bB, b_k1));
    const float vB0 = fmaf(w_v0, aB, fmaf(w_v1, bB, b_v0));
    const float vB1 = fmaf(w_v2, aB, fmaf(w_v3, bB, b_v1));

    {
        // thread w writes half-lane (w&1) of pair (w>>1)
        __half* k0h = reinterpret_cast<__half*>(k0s);
        __half* k1h = reinterpret_cast<__half*>(k1s);
        __half* v0h = reinterpret_cast<__half*>(v0s);
        __half* v1h = reinterpret_cast<__half*>(v1s);
        k0h[tid] = __float2half(kA0);  k1h[tid] = __float2half(kA1);
        v0h[tid] = __float2half(vA0);  v1h[tid] = __float2half(vA1);
        k0h[tid + 128] = __float2half(kB0);  k1h[tid + 128] = __float2half(kB1);
        v0h[tid + 128] = __float2half(vB0);  v1h[tid + 128] = __float2half(vB1);
    }

    // per-CTA max|k0|, max|k1| for the overflow-safe softmax bound
    float ak0 = fmaxf(fabsf(kA0), fabsf(kB0));
    float ak1 = fmaxf(fabsf(kA1), fabsf(kB1));
#pragma unroll
    for (int o = 16; o; o >>= 1) {
        ak0 = fmaxf(ak0, __shfl_xor_sync(0xffffffffu, ak0, o));
        ak1 = fmaxf(ak1, __shfl_xor_sync(0xffffffffu, ak1, o));
    }
    const int wid = tid >> 5;
    if ((tid & 31) == 0) { red[wid] = ak0; red[4 + wid] = ak1; }
    __syncthreads();

    float mk0 = fmaxf(fmaxf(red[0], red[1]), fmaxf(red[2], red[3]));
    float mk1 = fmaxf(fmaxf(red[4], red[5]), fmaxf(red[6], red[7]));

    const float L2E = 1.4426950408889634f;
    const float qA0e = qA0 * L2E, qA1e = qA1 * L2E;
    const float qB0e = qB0 * L2E, qB1e = qB1 * L2E;
    const float mhatA = fmaf(fabsf(qA0e), mk0, fabsf(qA1e) * mk1);
    const float mhatB = fmaf(fabsf(qB0e), mk0, fabsf(qB1e) * mk1);

    const __half2 qA0h = __float2half2_rn(qA0e);
    const __half2 qA1h = __float2half2_rn(qA1e);
    const __half2 qB0h = __float2half2_rn(qB0e);
    const __half2 qB1h = __float2half2_rn(qB1e);
    const __half2 mnAh = __float2half2_rn(-mhatA);
    const __half2 mnBh = __float2half2_rn(-mhatB);

    float fsA = 0.f, fA0 = 0.f, fA1 = 0.f;
    float fsB = 0.f, fB0 = 0.f, fB1 = 0.f;
    const __half2 hz = __float2half2_rn(0.f);

#pragma unroll 1
    for (int ch = 0; ch < 4; ++ch) {   // 4 chunks x 64 keys (32 pairs)
        // dual accumulator banks (even/odd pairs) -> halved dep chains
        __half2 sA[2] = {hz, hz}, A0[2] = {hz, hz}, A1[2] = {hz, hz};
        __half2 sB[2] = {hz, hz}, B0[2] = {hz, hz}, B1[2] = {hz, hz};
        const int p0 = ch * 32;
#pragma unroll 8
        for (int j = 0; j < 32; ++j) {  // pair = 2 keys
            const int p = p0 + j;
            const int bk2 = j & 1;
            const __half2 k0 = k0s[p];
            const __half2 k1 = k1s[p];
            const __half2 v0 = v0s[p];
            const __half2 v1 = v1s[p];

            const __half2 eA = h2exp2(__hfma2(qA0h, k0, __hfma2(qA1h, k1, mnAh)));
            const __half2 eB = h2exp2(__hfma2(qB0h, k0, __hfma2(qB1h, k1, mnBh)));

            sA[bk2] = __hadd2(sA[bk2], eA);
            sB[bk2] = __hadd2(sB[bk2], eB);
            A0[bk2] = __hfma2(eA, v0, A0[bk2]);
            A1[bk2] = __hfma2(eA, v1, A1[bk2]);
            B0[bk2] = __hfma2(eB, v0, B0[bk2]);
            B1[bk2] = __hfma2(eB, v1, B1[bk2]);
        }
        float2 t;
        t = __half22float2(__hadd2(sA[0], sA[1])); fsA += t.x + t.y;
        t = __half22float2(__hadd2(A0[0], A0[1])); fA0 += t.x + t.y;
        t = __half22float2(__hadd2(A1[0], A1[1])); fA1 += t.x + t.y;
        t = __half22float2(__hadd2(sB[0], sB[1])); fsB += t.x + t.y;
        t = __half22float2(__hadd2(B0[0], B0[1])); fB0 += t.x + t.y;
        t = __half22float2(__hadd2(B1[0], B1[1])); fB1 += t.x + t.y;
    }

    float invA, invB;
    asm("rcp.approx.ftz.f32 %0, %1;" : "=f"(invA) : "f"(fsA));
    asm("rcp.approx.ftz.f32 %0, %1;" : "=f"(invB) : "f"(fsB));

    out[base + tid]               = fmaf(fA0, invA, aA);
    out[PLANE + base + tid]       = fmaf(fA1, invA, bA);
    out[base + tid + 128]         = fmaf(fB0, invB, aB);
    out[PLANE + base + tid + 128] = fmaf(fB1, invB, bB);
}

extern "C" void kernel_launch(void* const* d_in, const int* in_sizes, int n_in,
                              void* d_out, int out_size)
{
    (void)in_sizes; (void)n_in; (void)out_size;
    channel_attn_kernel<<<BH_TOTAL, 128>>>(
        (const float*)d_in[0], (const float*)d_in[1],
        (const float*)d_in[2], (const float*)d_in[3],
        (const float*)d_in[4], (const float*)d_in[5],
        (const float*)d_in[6], (const float*)d_in[7],
        (float*)d_out);
}

// round 9
// speedup vs baseline: 1.0093x; 1.0023x over previous
#include <cuda_runtime.h>
#include <cuda_bf16.h>
#include <cstdint>

// ChannelSelfAttention: B=4,H=512,W=256. One CTA per (b,h), 128 threads,
// 2 queries/thread. Single-pass softmax with safe upper bound m_hat.
// Packed f32x2 math (FFMA2). R3 baseline (32.5us, MUFU 92% busy) + x=1/4
// of packed exp-pairs moved to an FMA-pipe poly exp2:
//  - branch-free (every quad: eA0/eA1/eB0 on MUFU, eB1 via poly)
//  - clamp-free splice: p >= -~60 always, so biased exp > 0; scale bits are
//    (t_bits << 23) + 0x3F800000 (2 ALU ops/lane on the idle ALU pipe)
//  - e = s * (1 + f*g(f)) form: 3-FMA Horner for g, deg-4 accuracy.

#define W_DIM 256
#define BH_TOTAL 2048
#define PLANE (2048 * 256)

__device__ __forceinline__ uint32_t smem_u32(const void* p) {
    uint32_t a;
    asm("{ .reg .u64 t; cvta.to.shared.u64 t, %1; cvt.u32.u64 %0, t; }"
        : "=r"(a) : "l"(p));
    return a;
}
__device__ __forceinline__ uint64_t pk2(float lo, float hi) {
    uint64_t r; asm("mov.b64 %0, {%1, %2};" : "=l"(r) : "f"(lo), "f"(hi)); return r;
}
__device__ __forceinline__ void upk2(float& lo, float& hi, uint64_t v) {
    asm("mov.b64 {%0, %1}, %2;" : "=f"(lo), "=f"(hi) : "l"(v));
}
__device__ __forceinline__ uint64_t fma2(uint64_t a, uint64_t b, uint64_t c) {
    uint64_t d; asm("fma.rn.f32x2 %0, %1, %2, %3;" : "=l"(d) : "l"(a), "l"(b), "l"(c)); return d;
}
__device__ __forceinline__ uint64_t add2(uint64_t a, uint64_t b) {
    uint64_t d; asm("add.rn.f32x2 %0, %1, %2;" : "=l"(d) : "l"(a), "l"(b)); return d;
}
__device__ __forceinline__ uint64_t mul2(uint64_t a, uint64_t b) {
    uint64_t d; asm("mul.rn.f32x2 %0, %1, %2;" : "=l"(d) : "l"(a), "l"(b)); return d;
}
__device__ __forceinline__ float ex2f(float x) {
    float r; asm("ex2.approx.ftz.f32 %0, %1;" : "=f"(r) : "f"(x)); return r;
}
__device__ __forceinline__ uint64_t mufu_exp2_2(uint64_t p2) {
    float pl, ph; upk2(pl, ph, p2);
    return pk2(ex2f(pl), ex2f(ph));
}

__global__ __launch_bounds__(128) void channel_attn_kernel(
    const float* __restrict__ x1, const float* __restrict__ x2,
    const float* __restrict__ wq, const float* __restrict__ bq,
    const float* __restrict__ wk, const float* __restrict__ bk,
    const float* __restrict__ wv, const float* __restrict__ bv,
    float* __restrict__ out)
{
    const int tid  = threadIdx.x;
    const int base = blockIdx.x * W_DIM;

    __shared__ __align__(16) float kArr[2 * W_DIM];
    __shared__ __align__(16) float vArr[2 * W_DIM];
    __shared__ float red[8];

    const float aA = x1[base + tid];
    const float bA = x2[base + tid];
    const float aB = x1[base + tid + 128];
    const float bB = x2[base + tid + 128];

    const float w_q0 = wq[0], w_q1 = wq[1], w_q2 = wq[2], w_q3 = wq[3];
    const float w_k0 = wk[0], w_k1 = wk[1], w_k2 = wk[2], w_k3 = wk[3];
    const float w_v0 = wv[0], w_v1 = wv[1], w_v2 = wv[2], w_v3 = wv[3];
    const float b_q0 = bq[0], b_q1 = bq[1];
    const float b_k0 = bk[0], b_k1 = bk[1];
    const float b_v0 = bv[0], b_v1 = bv[1];

    const float qA0 = fmaf(w_q0, aA, fmaf(w_q1, bA, b_q0));
    const float qA1 = fmaf(w_q2, aA, fmaf(w_q3, bA, b_q1));
    const float kA0 = fmaf(w_k0, aA, fmaf(w_k1, bA, b_k0));
    const float kA1 = fmaf(w_k2, aA, fmaf(w_k3, bA, b_k1));
    const float vA0 = fmaf(w_v0, aA, fmaf(w_v1, bA, b_v0));
    const float vA1 = fmaf(w_v2, aA, fmaf(w_v3, bA, b_v1));

    const float qB0 = fmaf(w_q0, aB, fmaf(w_q1, bB, b_q0));
    const float qB1 = fmaf(w_q2, aB, fmaf(w_q3, bB, b_q1));
    const float kB0 = fmaf(w_k0, aB, fmaf(w_k1, bB, b_k0));
    const float kB1 = fmaf(w_k2, aB, fmaf(w_k3, bB, b_k1));
    const float vB0 = fmaf(w_v0, aB, fmaf(w_v1, bB, b_v0));
    const float vB1 = fmaf(w_v2, aB, fmaf(w_v3, bB, b_v1));

    {
        int j = tid >> 1, h = tid & 1;
        kArr[4 * j + h] = kA0;  kArr[4 * j + 2 + h] = kA1;
        vArr[4 * j + h] = vA0;  vArr[4 * j + 2 + h] = vA1;
        int w2 = tid + 128;
        j = w2 >> 1; h = w2 & 1;
        kArr[4 * j + h] = kB0;  kArr[4 * j + 2 + h] = kB1;
        vArr[4 * j + h] = vB0;  vArr[4 * j + 2 + h] = vB1;
    }

    float ak0 = fmaxf(fabsf(kA0), fabsf(kB0));
    float ak1 = fmaxf(fabsf(kA1), fabsf(kB1));
#pragma unroll
    for (int o = 16; o; o >>= 1) {
        ak0 = fmaxf(ak0, __shfl_xor_sync(0xffffffffu, ak0, o));
        ak1 = fmaxf(ak1, __shfl_xor_sync(0xffffffffu, ak1, o));
    }
    const int wid = tid >> 5;
    if ((tid & 31) == 0) { red[wid] = ak0; red[4 + wid] = ak1; }
    __syncthreads();

    float mk0 = fmaxf(fmaxf(red[0], red[1]), fmaxf(red[2], red[3]));
    float mk1 = fmaxf(fmaxf(red[4], red[5]), fmaxf(red[6], red[7]));

    const float L2E = 1.4426950408889634f;
    const float qA0e = qA0 * L2E, qA1e = qA1 * L2E;
    const float qB0e = qB0 * L2E, qB1e = qB1 * L2E;
    const float mhatA = fmaf(fabsf(qA0e), mk0, fabsf(qA1e) * mk1);
    const float mhatB = fmaf(fabsf(qB0e), mk0, fabsf(qB1e) * mk1);

    const uint64_t qA0_2 = pk2(qA0e, qA0e), qA1_2 = pk2(qA1e, qA1e);
    const uint64_t qB0_2 = pk2(qB0e, qB0e), qB1_2 = pk2(qB1e, qB1e);
    const uint64_t mnA2 = pk2(-mhatA, -mhatA), mnB2 = pk2(-mhatB, -mhatB);

    // poly exp2 constants (g(f) = (2^f-1)/f Horner, deg-4 overall)
    const float MGC = 12582912.0f;  // 2^23 + 2^22
    const uint64_t MAGIC2  = pk2(MGC, MGC);
    const uint64_t NMAGIC2 = pk2(-MGC, -MGC);
    const uint64_t NONE2   = pk2(-1.0f, -1.0f);
    const uint64_t C4 = pk2(0.00961813f, 0.00961813f);
    const uint64_t C3 = pk2(0.05550411f, 0.05550411f);
    const uint64_t C2 = pk2(0.24022651f, 0.24022651f);
    const uint64_t C1 = pk2(0.69314718f, 0.69314718f);

    uint64_t sumA = 0ull, accA0 = 0ull, accA1 = 0ull;
    uint64_t sumB = 0ull, accB0 = 0ull, accB1 = 0ull;

    const uint32_t kb = smem_u32(kArr);
    const uint32_t vb = smem_u32(vArr);

#pragma unroll 4
    for (int qd = 0; qd < W_DIM / 4; ++qd) {  // 4 keys per iteration
        uint64_t K0a, K0b, K1a, K1b, V0a, V0b, V1a, V1b;
        asm("ld.shared.v2.u64 {%0, %1}, [%2];"
            : "=l"(K0a), "=l"(K0b) : "r"(kb + 32u * qd));
        asm("ld.shared.v2.u64 {%0, %1}, [%2];"
            : "=l"(K1a), "=l"(K1b) : "r"(kb + 32u * qd + 16u));
        asm("ld.shared.v2.u64 {%0, %1}, [%2];"
            : "=l"(V0a), "=l"(V0b) : "r"(vb + 32u * qd));
        asm("ld.shared.v2.u64 {%0, %1}, [%2];"
            : "=l"(V1a), "=l"(V1b) : "r"(vb + 32u * qd + 16u));

        const uint64_t pA0 = fma2(qA0_2, K0a, fma2(qA1_2, K0b, mnA2));
        const uint64_t pA1 = fma2(qA0_2, K1a, fma2(qA1_2, K1b, mnA2));
        const uint64_t pB0 = fma2(qB0_2, K0a, fma2(qB1_2, K0b, mnB2));
        const uint64_t pB1 = fma2(qB0_2, K1a, fma2(qB1_2, K1b, mnB2));

        const uint64_t eA0 = mufu_exp2_2(pA0);
        const uint64_t eA1 = mufu_exp2_2(pA1);
        const uint64_t eB0 = mufu_exp2_2(pB0);

        // eB1 via FMA-pipe poly (branch-free, every quad): e = s*(1 + f*g)
        uint64_t eB1;
        {
            const uint64_t t2 = add2(pB1, MAGIC2);    // int bits of round(p)
            const uint64_t r2 = add2(t2, NMAGIC2);    // r = round(p) as float
            const uint64_t f2 = fma2(r2, NONE2, pB1); // f = p - r, [-0.5,0.5]
            uint64_t g = fma2(f2, C4, C3);
            g = fma2(f2, g, C2);
            g = fma2(f2, g, C1);
            uint32_t tl, th;
            asm("mov.b64 {%0, %1}, %2;" : "=r"(tl), "=r"(th) : "l"(t2));
            // s = 2^round(p): (n+127)<<23 == (t_bits<<23) + 0x3F800000
            const uint32_t sl = (tl << 23) + 0x3F800000u;
            const uint32_t sh = (th << 23) + 0x3F800000u;
            uint64_t s2;
            asm("mov.b64 %0, {%1, %2};" : "=l"(s2) : "r"(sl), "r"(sh));
            eB1 = fma2(mul2(s2, f2), g, s2);
        }

        sumA = add2(sumA, add2(eA0, eA1));
        sumB = add2(sumB, add2(eB0, eB1));
        accA0 = fma2(eA0, V0a, accA0);
        accA0 = fma2(eA1, V1a, accA0);
        accA1 = fma2(eA0, V0b, accA1);
        accA1 = fma2(eA1, V1b, accA1);
        accB0 = fma2(eB0, V0a, accB0);
        accB0 = fma2(eB1, V1a, accB0);
        accB1 = fma2(eB0, V0b, accB1);
        accB1 = fma2(eB1, V1b, accB1);
    }

    float sl, sh, x0l, x0h, x1l, x1h;
    float invA, invB;

    upk2(sl, sh, sumA);
    asm("rcp.approx.ftz.f32 %0, %1;" : "=f"(invA) : "f"(sl + sh));
    upk2(sl, sh, sumB);
    asm("rcp.approx.ftz.f32 %0, %1;" : "=f"(invB) : "f"(sl + sh));

    upk2(x0l, x0h, accA0);
    upk2(x1l, x1h, accA1);
    out[base + tid]          = fmaf(x0l + x0h, invA, aA);
    out[PLANE + base + tid]  = fmaf(x1l + x1h, invA, bA);

    upk2(x0l, x0h, accB0);
    upk2(x1l, x1h, accB1);
    out[base + tid + 128]         = fmaf(x0l + x0h, invB, aB);
    out[PLANE + base + tid + 128] = fmaf(x1l + x1h, invB, bB);
}

extern "C" void kernel_launch(void* const* d_in, const int* in_sizes, int n_in,
                              void* d_out, int out_size)
{
    (void)in_sizes; (void)n_in; (void)out_size;
    channel_attn_kernel<<<BH_TOTAL, 128>>>(
        (const float*)d_in[0], (const float*)d_in[1],
        (const float*)d_in[2], (const float*)d_in[3],
        (const float*)d_in[4], (const float*)d_in[5],
        (const float*)d_in[6], (const float*)d_in[7],
        (float*)d_out);
}

// round 10
// speedup vs baseline: 1.2551x; 1.2435x over previous
#include <cuda_runtime.h>
#include <cuda_bf16.h>
#include <cstdint>

// ChannelSelfAttention: B=4,H=512,W=256. 2048 independent W x W attentions
// over a 2-channel feature. TWO heads per CTA (grid 1024 x 256 threads):
// threads 0-127 process head 2*blk, threads 128-255 head 2*blk+1, each
// thread owning two query positions (t, t+128) of its head. The hot loop is
// byte-identical to the best R3 kernel (MUFU-floor bound, 92% busy); the
// 256-thread CTAs raise occupancy 46% -> ~62% to close the last 8%.

#define W_DIM 256
#define BH_TOTAL 2048
#define PLANE (2048 * 256)

__device__ __forceinline__ uint32_t smem_u32(const void* p) {
    uint32_t a;
    asm("{ .reg .u64 t; cvta.to.shared.u64 t, %1; cvt.u32.u64 %0, t; }"
        : "=r"(a) : "l"(p));
    return a;
}
__device__ __forceinline__ uint64_t pk2(float lo, float hi) {
    uint64_t r; asm("mov.b64 %0, {%1, %2};" : "=l"(r) : "f"(lo), "f"(hi)); return r;
}
__device__ __forceinline__ void upk2(float& lo, float& hi, uint64_t v) {
    asm("mov.b64 {%0, %1}, %2;" : "=f"(lo), "=f"(hi) : "l"(v));
}
__device__ __forceinline__ uint64_t fma2(uint64_t a, uint64_t b, uint64_t c) {
    uint64_t d; asm("fma.rn.f32x2 %0, %1, %2, %3;" : "=l"(d) : "l"(a), "l"(b), "l"(c)); return d;
}
__device__ __forceinline__ uint64_t add2(uint64_t a, uint64_t b) {
    uint64_t d; asm("add.rn.f32x2 %0, %1, %2;" : "=l"(d) : "l"(a), "l"(b)); return d;
}
__device__ __forceinline__ float ex2f(float x) {
    float r; asm("ex2.approx.ftz.f32 %0, %1;" : "=f"(r) : "f"(x)); return r;
}
__device__ __forceinline__ uint64_t mufu_exp2_2(uint64_t p2) {
    float pl, ph; upk2(pl, ph, p2);
    return pk2(ex2f(pl), ex2f(ph));
}

__global__ __launch_bounds__(256) void channel_attn_kernel(
    const float* __restrict__ x1, const float* __restrict__ x2,
    const float* __restrict__ wq, const float* __restrict__ bq,
    const float* __restrict__ wk, const float* __restrict__ bk,
    const float* __restrict__ wv, const float* __restrict__ bv,
    float* __restrict__ out)
{
    const int tid  = threadIdx.x;
    const int head = tid >> 7;          // 0 or 1 within this CTA
    const int t    = tid & 127;         // lane within head
    const int base = (blockIdx.x * 2 + head) * W_DIM;

    // Per-head pairwise SoA: pair j holds (k0[2j],k0[2j+1],k1[2j],k1[2j+1])
    __shared__ __align__(16) float kArr[2][2 * W_DIM];
    __shared__ __align__(16) float vArr[2][2 * W_DIM];
    __shared__ float red[16];           // [head*8 + {0..3}: ak0, {4..7}: ak1]

    const float aA = x1[base + t];
    const float bA = x2[base + t];
    const float aB = x1[base + t + 128];
    const float bB = x2[base + t + 128];

    const float w_q0 = wq[0], w_q1 = wq[1], w_q2 = wq[2], w_q3 = wq[3];
    const float w_k0 = wk[0], w_k1 = wk[1], w_k2 = wk[2], w_k3 = wk[3];
    const float w_v0 = wv[0], w_v1 = wv[1], w_v2 = wv[2], w_v3 = wv[3];
    const float b_q0 = bq[0], b_q1 = bq[1];
    const float b_k0 = bk[0], b_k1 = bk[1];
    const float b_v0 = bv[0], b_v1 = bv[1];

    const float qA0 = fmaf(w_q0, aA, fmaf(w_q1, bA, b_q0));
    const float qA1 = fmaf(w_q2, aA, fmaf(w_q3, bA, b_q1));
    const float kA0 = fmaf(w_k0, aA, fmaf(w_k1, bA, b_k0));
    const float kA1 = fmaf(w_k2, aA, fmaf(w_k3, bA, b_k1));
    const float vA0 = fmaf(w_v0, aA, fmaf(w_v1, bA, b_v0));
    const float vA1 = fmaf(w_v2, aA, fmaf(w_v3, bA, b_v1));

    const float qB0 = fmaf(w_q0, aB, fmaf(w_q1, bB, b_q0));
    const float qB1 = fmaf(w_q2, aB, fmaf(w_q3, bB, b_q1));
    const float kB0 = fmaf(w_k0, aB, fmaf(w_k1, bB, b_k0));
    const float kB1 = fmaf(w_k2, aB, fmaf(w_k3, bB, b_k1));
    const float vB0 = fmaf(w_v0, aB, fmaf(w_v1, bB, b_v0));
    const float vB1 = fmaf(w_v2, aB, fmaf(w_v3, bB, b_v1));

    {
        int j = t >> 1, h = t & 1;
        kArr[head][4 * j + h] = kA0;  kArr[head][4 * j + 2 + h] = kA1;
        vArr[head][4 * j + h] = vA0;  vArr[head][4 * j + 2 + h] = vA1;
        int w2 = t + 128;
        j = w2 >> 1; h = w2 & 1;
        kArr[head][4 * j + h] = kB0;  kArr[head][4 * j + 2 + h] = kB1;
        vArr[head][4 * j + h] = vB0;  vArr[head][4 * j + 2 + h] = vB1;
    }

    // per-head max|k0|, max|k1| for the overflow-safe softmax bound
    float ak0 = fmaxf(fabsf(kA0), fabsf(kB0));
    float ak1 = fmaxf(fabsf(kA1), fabsf(kB1));
#pragma unroll
    for (int o = 16; o; o >>= 1) {
        ak0 = fmaxf(ak0, __shfl_xor_sync(0xffffffffu, ak0, o));
        ak1 = fmaxf(ak1, __shfl_xor_sync(0xffffffffu, ak1, o));
    }
    const int wh = (tid >> 5) & 3;      // warp index within head (0..3)
    if ((tid & 31) == 0) { red[head * 8 + wh] = ak0; red[head * 8 + 4 + wh] = ak1; }
    __syncthreads();

    const float* rh = &red[head * 8];
    float mk0 = fmaxf(fmaxf(rh[0], rh[1]), fmaxf(rh[2], rh[3]));
    float mk1 = fmaxf(fmaxf(rh[4], rh[5]), fmaxf(rh[6], rh[7]));

    const float L2E = 1.4426950408889634f;
    const float qA0e = qA0 * L2E, qA1e = qA1 * L2E;
    const float qB0e = qB0 * L2E, qB1e = qB1 * L2E;
    const float mhatA = fmaf(fabsf(qA0e), mk0, fabsf(qA1e) * mk1);
    const float mhatB = fmaf(fabsf(qB0e), mk0, fabsf(qB1e) * mk1);

    const uint64_t qA0_2 = pk2(qA0e, qA0e), qA1_2 = pk2(qA1e, qA1e);
    const uint64_t qB0_2 = pk2(qB0e, qB0e), qB1_2 = pk2(qB1e, qB1e);
    const uint64_t mnA2 = pk2(-mhatA, -mhatA), mnB2 = pk2(-mhatB, -mhatB);

    uint64_t sumA = 0ull, accA0 = 0ull, accA1 = 0ull;
    uint64_t sumB = 0ull, accB0 = 0ull, accB1 = 0ull;

    const uint32_t kb = smem_u32(&kArr[head][0]);
    const uint32_t vb = smem_u32(&vArr[head][0]);

#pragma unroll 4
    for (int qd = 0; qd < W_DIM / 4; ++qd) {  // 4 keys per iteration
        uint64_t K0a, K0b, K1a, K1b, V0a, V0b, V1a, V1b;
        asm("ld.shared.v2.u64 {%0, %1}, [%2];"
            : "=l"(K0a), "=l"(K0b) : "r"(kb + 32u * qd));
        asm("ld.shared.v2.u64 {%0, %1}, [%2];"
            : "=l"(K1a), "=l"(K1b) : "r"(kb + 32u * qd + 16u));
        asm("ld.shared.v2.u64 {%0, %1}, [%2];"
            : "=l"(V0a), "=l"(V0b) : "r"(vb + 32u * qd));
        asm("ld.shared.v2.u64 {%0, %1}, [%2];"
            : "=l"(V1a), "=l"(V1b) : "r"(vb + 32u * qd + 16u));

        const uint64_t pA0 = fma2(qA0_2, K0a, fma2(qA1_2, K0b, mnA2));
        const uint64_t pA1 = fma2(qA0_2, K1a, fma2(qA1_2, K1b, mnA2));
        const uint64_t pB0 = fma2(qB0_2, K0a, fma2(qB1_2, K0b, mnB2));
        const uint64_t pB1 = fma2(qB0_2, K1a, fma2(qB1_2, K1b, mnB2));

        const uint64_t eA0 = mufu_exp2_2(pA0);
        const uint64_t eA1 = mufu_exp2_2(pA1);
        const uint64_t eB0 = mufu_exp2_2(pB0);
        const uint64_t eB1 = mufu_exp2_2(pB1);

        sumA = add2(sumA, add2(eA0, eA1));
        sumB = add2(sumB, add2(eB0, eB1));
        accA0 = fma2(eA0, V0a, accA0);
        accA0 = fma2(eA1, V1a, accA0);
        accA1 = fma2(eA0, V0b, accA1);
        accA1 = fma2(eA1, V1b, accA1);
        accB0 = fma2(eB0, V0a, accB0);
        accB0 = fma2(eB1, V1a, accB0);
        accB1 = fma2(eB0, V0b, accB1);
        accB1 = fma2(eB1, V1b, accB1);
    }

    float sl, sh, x0l, x0h, x1l, x1h;
    float invA, invB;

    upk2(sl, sh, sumA);
    asm("rcp.approx.ftz.f32 %0, %1;" : "=f"(invA) : "f"(sl + sh));
    upk2(sl, sh, sumB);
    asm("rcp.approx.ftz.f32 %0, %1;" : "=f"(invB) : "f"(sl + sh));

    upk2(x0l, x0h, accA0);
    upk2(x1l, x1h, accA1);
    out[base + t]          = fmaf(x0l + x0h, invA, aA);
    out[PLANE + base + t]  = fmaf(x1l + x1h, invA, bA);

    upk2(x0l, x0h, accB0);
    upk2(x1l, x1h, accB1);
    out[base + t + 128]         = fmaf(x0l + x0h, invB, aB);
    out[PLANE + base + t + 128] = fmaf(x1l + x1h, invB, bB);
}

extern "C" void kernel_launch(void* const* d_in, const int* in_sizes, int n_in,
                              void* d_out, int out_size)
{
    (void)in_sizes; (void)n_in; (void)out_size;
    channel_attn_kernel<<<BH_TOTAL / 2, 256>>>(
        (const float*)d_in[0], (const float*)d_in[1],
        (const float*)d_in[2], (const float*)d_in[3],
        (const float*)d_in[4], (const float*)d_in[5],
        (const float*)d_in[6], (const float*)d_in[7],
        (float*)d_out);
}